// round 7
// baseline (speedup 1.0000x reference)
#include <cuda_runtime.h>

#define Bn 32
#define Cn 32
#define Gn 4096
#define Nn 16384
#define Hn 64
#define SCAT_BLOCKS Bn                    // one scatter block per batch
#define CG_BLOCKS ((Bn * Gn) / 256)       // 512 cellgemm blocks (256 cells each)

typedef unsigned long long u64;

// slot -> cell index (materialized by scatter; replaces searchsorted)
__device__ int g_idx[Bn * Nn];
// per-cell layer-1 pre-activations, transposed + h-paired:
// g_Au[((b*32 + hp) * Gn) + cell] = pk(pre[2hp], pre[2hp+1])   (32 MB)
__device__ u64 g_Au[(size_t)Bn * (Hn / 2) * Gn];

// ---- packed f32x2 helpers --------------------------------------------------
static __device__ __forceinline__ u64 pk(float lo, float hi) {
    u64 r; asm("mov.b64 %0, {%1, %2};" : "=l"(r) : "f"(lo), "f"(hi)); return r;
}
static __device__ __forceinline__ void upk(float& lo, float& hi, u64 v) {
    asm("mov.b64 {%0, %1}, %2;" : "=f"(lo), "=f"(hi) : "l"(v));
}
static __device__ __forceinline__ u64 fma2(u64 a, u64 b, u64 c) {
    u64 d; asm("fma.rn.f32x2 %0, %1, %2, %3;" : "=l"(d) : "l"(a), "l"(b), "l"(c));
    return d;
}

// ---- weight blob in GLOBAL memory (staged into shared by each block) -------
struct __align__(16) WBlob {
    u64 w1T[Cn][32];     // [c][hp] = pk(W1[2hp][c], W1[2hp+1][c])
    u64 b1p[32];         // pk(b1[2hp], b1[2hp+1])
    u64 w3233i[64];      // [2hp]=pk(W1[2hp][32],W1[2hp+1][32]), [2hp+1]=same for col 33
    u64 w2xyi[64];       // [2hp]=pk(W2x pair), [2hp+1]=pk(W2y pair)
    u64 w2zp[32];        // pk(W2z pair)
    float b2v[4];
};
__device__ WBlob g_blob;

// ---------------------------------------------------------------------------
// Kernel 0: weight transform (5 blocks).
// ---------------------------------------------------------------------------
__global__ __launch_bounds__(256) void wtrans_kernel(const float* __restrict__ W1,
                                                     const float* __restrict__ b1,
                                                     const float* __restrict__ W2,
                                                     const float* __restrict__ b2)
{
    const int t = threadIdx.x;
    if (blockIdx.x < 4) {
        const int i = blockIdx.x * 256 + t;      // 1024 w1T entries
        const int c = i >> 5, hp = i & 31;
        g_blob.w1T[c][hp] = pk(W1[(2 * hp) * 34 + c], W1[(2 * hp + 1) * 34 + c]);
        return;
    }
    if (t < 32) {
        g_blob.b1p[t]        = pk(b1[2 * t], b1[2 * t + 1]);
        g_blob.w3233i[2 * t]     = pk(W1[(2 * t) * 34 + 32], W1[(2 * t + 1) * 34 + 32]);
        g_blob.w3233i[2 * t + 1] = pk(W1[(2 * t) * 34 + 33], W1[(2 * t + 1) * 34 + 33]);
        g_blob.w2xyi[2 * t]      = pk(W2[2 * t],          W2[2 * t + 1]);
        g_blob.w2xyi[2 * t + 1]  = pk(W2[Hn + 2 * t],     W2[Hn + 2 * t + 1]);
        g_blob.w2zp[t]           = pk(W2[2 * Hn + 2 * t], W2[2 * Hn + 2 * t + 1]);
    }
    if (t < 3) g_blob.b2v[t] = b2[t];
    if (t == 3) g_blob.b2v[3] = 0.f;
}

// ---------------------------------------------------------------------------
// Kernel 1 (fused): blocks [0, SCAT_BLOCKS): cumsum + direct index scatter.
//                   blocks [SCAT_BLOCKS, +CG_BLOCKS): per-cell layer-1 GEMM.
// ---------------------------------------------------------------------------
__global__ __launch_bounds__(256) void fused_kernel(const float* __restrict__ x,
                                                    const int* __restrict__ counts)
{
    __shared__ u64 w1Ts[Cn * 32];   // 8 KB
    __shared__ u64 b1s[32];
    __shared__ int wsum[8];

    const int t = threadIdx.x;

    if (blockIdx.x < SCAT_BLOCKS) {
        // ---- cumsum + scatter for one batch ----
        const int b = blockIdx.x;
        const int lane = t & 31;
        const int w    = t >> 5;
        const int base = t * 16;                 // 16 cells per thread

        int local[16];
        int s = 0;
#pragma unroll
        for (int i = 0; i < 16; i++) {
            s += counts[b * Gn + base + i];
            local[i] = s;
        }
        int v = s;
#pragma unroll
        for (int d = 1; d < 32; d <<= 1) {
            int u = __shfl_up_sync(0xffffffff, v, d);
            if (lane >= d) v += u;
        }
        if (lane == 31) wsum[w] = v;
        __syncthreads();
        int woff = 0;
        for (int i = 0; i < w; i++) woff += wsum[i];
        const int excl = woff + v - s;

        int* gi = g_idx + b * Nn;
        int start = excl;
#pragma unroll
        for (int i = 0; i < 16; i++) {
            const int end = excl + local[i];
            const int cell = base + i;
            for (int j = start; j < end; j++) gi[j] = cell;
            start = end;
        }
        return;
    }

    // ---- per-cell layer-1 GEMM: 2 cells x 16 hp per thread ----
    // stage weights into shared
    const u64* gw = &g_blob.w1T[0][0];
    for (int i = t; i < Cn * 32; i += 256) w1Ts[i] = __ldg(gw + i);
    if (t < 32) b1s[t] = __ldg(&g_blob.b1p[t]);
    __syncthreads();

    const int blockCell0 = (blockIdx.x - SCAT_BLOCKS) * 256;   // 256 cells/block
    const int b   = blockCell0 >> 12;                          // / Gn (same for block)
    const int cp  = t & 127;                                   // cell-pair in block
    const int hf  = t >> 7;                                    // 0: hp 0..15, 1: 16..31
    const int hp0 = hf * 16;
    const int cell0 = (blockCell0 & (Gn - 1)) + 2 * cp;        // even

    u64 acc0[16], acc1[16];
#pragma unroll
    for (int m = 0; m < 16; m++) { acc0[m] = b1s[hp0 + m]; acc1[m] = acc0[m]; }

    const float2* xb = reinterpret_cast<const float2*>(
        x + (size_t)b * Cn * Gn + cell0);
#pragma unroll 4
    for (int c = 0; c < Cn; c++) {
        float2 xv = __ldg(xb + c * (Gn / 2));
        const u64 xp0 = pk(xv.x, xv.x);
        const u64 xp1 = pk(xv.y, xv.y);
        const ulonglong2* wr = reinterpret_cast<const ulonglong2*>(&w1Ts[c * 32 + hp0]);
#pragma unroll
        for (int q = 0; q < 8; q++) {
            ulonglong2 wv = wr[q];
            acc0[2 * q]     = fma2(wv.x, xp0, acc0[2 * q]);
            acc1[2 * q]     = fma2(wv.x, xp1, acc1[2 * q]);
            acc0[2 * q + 1] = fma2(wv.y, xp0, acc0[2 * q + 1]);
            acc1[2 * q + 1] = fma2(wv.y, xp1, acc1[2 * q + 1]);
        }
    }

    // coalesced STG.128: adjacent cells packed per hp row
#pragma unroll
    for (int m = 0; m < 16; m++) {
        ulonglong2* dst = reinterpret_cast<ulonglong2*>(
            g_Au + ((size_t)b * 32 + hp0 + m) * Gn + cell0);
        *dst = make_ulonglong2(acc0[m], acc1[m]);
    }
}

// ---------------------------------------------------------------------------
// Kernel 2: per-point tail: idx lookup + transposed-A gather + tiny MLP.
// ---------------------------------------------------------------------------
__global__ __launch_bounds__(256) void mlp_kernel(
    const float* __restrict__ b_rnd,   // (B, 2, N)
    const float* __restrict__ grid_o,  // (3, G)
    float* __restrict__ out,           // (B, 3, N)
    float* __restrict__ reg_out)       // (B, N)
{
    __shared__ u64 w3233s[64];
    __shared__ u64 w2xys[64];
    __shared__ u64 w2zs[32];
    __shared__ float b2s[4];

    const int t = threadIdx.x;
    if (t < 64) {
        w3233s[t] = __ldg(&g_blob.w3233i[t]);
        w2xys[t]  = __ldg(&g_blob.w2xyi[t]);
    }
    if (t < 32) w2zs[t] = __ldg(&g_blob.w2zp[t]);
    if (t < 4)  b2s[t]  = __ldg(&g_blob.b2v[t]);
    __syncthreads();

    const int gid = blockIdx.x * 256 + t;            // covers Bn*Nn
    const int b = gid >> 14;                         // / Nn
    const int j = gid & (Nn - 1);

    const int idx = __ldg(g_idx + b * Nn + j);

    // gather 32 packed pre-activation pairs (idx monotone -> near-broadcast)
    u64 a2[32];
    const u64* Ab = g_Au + (size_t)b * 32 * Gn + idx;
#pragma unroll
    for (int hp = 0; hp < 32; hp++) a2[hp] = __ldg(Ab + hp * Gn);

    const float* br = b_rnd + (size_t)b * 2 * Nn;
    const float r0 = br[j], r1 = br[Nn + j];
    const u64 rp0 = pk(r0, r0), rp1 = pk(r1, r1);

    u64 oX2 = 0ull, oY2 = 0ull, oZ2 = 0ull;
    const ulonglong2* w3233v = reinterpret_cast<const ulonglong2*>(w3233s);
    const ulonglong2* w2xyv  = reinterpret_cast<const ulonglong2*>(w2xys);
#pragma unroll
    for (int hp = 0; hp < 32; hp++) {
        ulonglong2 wA = w3233v[hp];
        u64 pre = fma2(wA.x, rp0, a2[hp]);
        pre     = fma2(wA.y, rp1, pre);
        float plo, phi;
        upk(plo, phi, pre);
        plo = fmaxf(plo, 0.f);
        phi = fmaxf(phi, 0.f);
        u64 act = pk(plo, phi);
        ulonglong2 w2 = w2xyv[hp];
        oX2 = fma2(w2.x, act, oX2);
        oY2 = fma2(w2.y, act, oY2);
        oZ2 = fma2(w2zs[hp], act, oZ2);
    }

    float xl, xh, yl, yh, zl, zh;
    upk(xl, xh, oX2); upk(yl, yh, oY2); upk(zl, zh, oZ2);
    const float o0 = b2s[0] + xl + xh;
    const float o1 = b2s[1] + yl + yh;
    const float o2 = b2s[2] + zl + zh;

    const float thr = 0.10825317547305482f;  // sqrt(3)/16
    const float nrm = sqrtf(o0 * o0 + o1 * o1 + o2 * o2);

    float* outb = out + (size_t)b * 3 * Nn;
    outb[j]          = o0 + __ldg(grid_o + idx);
    outb[Nn + j]     = o1 + __ldg(grid_o + Gn + idx);
    outb[2 * Nn + j] = o2 + __ldg(grid_o + 2 * Gn + idx);
    reg_out[b * Nn + j] = fmaxf(nrm - thr, 0.f);
}

extern "C" void kernel_launch(void* const* d_in, const int* in_sizes, int n_in,
                              void* d_out, int out_size)
{
    const float* x      = (const float*)d_in[0];
    const int*   counts = (const int*)  d_in[1];
    const float* b_rnd  = (const float*)d_in[2];
    const float* grid_o = (const float*)d_in[3];
    const float* W1     = (const float*)d_in[4];
    const float* b1     = (const float*)d_in[5];
    const float* W2     = (const float*)d_in[6];
    const float* b2     = (const float*)d_in[7];

    float* out     = (float*)d_out;              // (B, 3, N)
    float* reg_out = out + (size_t)Bn * 3 * Nn;  // (B, N)

    wtrans_kernel<<<5, 256>>>(W1, b1, W2, b2);
    fused_kernel<<<SCAT_BLOCKS + CG_BLOCKS, 256>>>(x, counts);
    mlp_kernel<<<(Bn * Nn) / 256, 256>>>(b_rnd, grid_o, out, reg_out);
}